// round 1
// baseline (speedup 1.0000x reference)
#include <cuda_runtime.h>
#include <cuda_bf16.h>

// Problem constants (fixed by the dataset): B=4, C=5, H=64, W=64, N=4096
#define BB 4
#define CC 5
#define HH 64
#define WW 64
#define HW 4096            // H*W
#define BSTRIDE 20480      // C*HW
#define NMAX 4096
#define M_TILE 8           // queries per block

// -------- scratch (device globals; no allocation allowed) --------
__device__ float g_kf[BB * CC * HW];
__device__ float g_vf[BB * CC * HW];
__device__ float g_q[NMAX * CC];
__device__ int   g_perm[NMAX];
__device__ int   g_off[BB + 1];

// ---------------------------------------------------------------
// Kernel 1: compute k = Kw@x+kb, v = Vw@x+vb for every (b,p); also y = x copy.
// grid 64 x 256 threads, one thread per (b,p).
// ---------------------------------------------------------------
__global__ void kv_kernel(const float* __restrict__ x,
                          const float* __restrict__ kw, const float* __restrict__ kb,
                          const float* __restrict__ vw, const float* __restrict__ vb,
                          float* __restrict__ y) {
    __shared__ float skw[25], skb[5], svw[25], svb[5];
    int tid = threadIdx.x;
    if (tid < 25) { skw[tid] = kw[tid]; svw[tid] = vw[tid]; }
    if (tid < 5)  { skb[tid] = kb[tid]; svb[tid] = vb[tid]; }
    __syncthreads();

    int t = blockIdx.x * blockDim.x + tid;   // 0..16383
    int b = t >> 12;
    int p = t & (HW - 1);
    const float* xb = x + b * BSTRIDE + p;
    float* yb = y + b * BSTRIDE + p;

    float xs[CC];
#pragma unroll
    for (int c = 0; c < CC; c++) {
        xs[c] = xb[c * HW];
        yb[c * HW] = xs[c];              // y = x (scatter overwrites later)
    }
#pragma unroll
    for (int o = 0; o < CC; o++) {
        float k = skb[o], v = svb[o];
#pragma unroll
        for (int c = 0; c < CC; c++) {
            k = fmaf(skw[o * CC + c], xs[c], k);
            v = fmaf(svw[o * CC + c], xs[c], v);
        }
        g_kf[b * BSTRIDE + o * HW + p] = k;
        g_vf[b * BSTRIDE + o * HW + p] = v;
    }
}

// ---------------------------------------------------------------
// Kernel 2: q[n] = Qw @ x[idx] + qb for each query index
// ---------------------------------------------------------------
__global__ void q_kernel(const float* __restrict__ x,
                         const float* __restrict__ qw, const float* __restrict__ qb,
                         const int* __restrict__ ib, const int* __restrict__ ih,
                         const int* __restrict__ iw, int n) {
    __shared__ float sw[25], sb[5];
    int tid = threadIdx.x;
    if (tid < 25) sw[tid] = qw[tid];
    if (tid < 5)  sb[tid] = qb[tid];
    __syncthreads();

    int i = blockIdx.x * blockDim.x + tid;
    if (i >= n) return;
    int b = ib[i];
    int pix = ih[i] * WW + iw[i];
    const float* xb = x + b * BSTRIDE + pix;
    float xs[CC];
#pragma unroll
    for (int c = 0; c < CC; c++) xs[c] = xb[c * HW];
#pragma unroll
    for (int o = 0; o < CC; o++) {
        float q = sb[o];
#pragma unroll
        for (int c = 0; c < CC; c++) q = fmaf(sw[o * CC + c], xs[c], q);
        g_q[i * CC + o] = q;
    }
}

// ---------------------------------------------------------------
// Kernel 3: group query indices by batch (counting sort, single block)
// ---------------------------------------------------------------
__global__ void group_kernel(const int* __restrict__ ib, int n) {
    __shared__ int scnt[BB];
    __shared__ int soff[BB];
    int tid = threadIdx.x;
    if (tid < BB) scnt[tid] = 0;
    __syncthreads();
    for (int i = tid; i < n; i += blockDim.x) atomicAdd(&scnt[ib[i]], 1);
    __syncthreads();
    if (tid == 0) {
        int acc = 0;
        for (int b = 0; b < BB; b++) { g_off[b] = acc; soff[b] = acc; acc += scnt[b]; }
        g_off[BB] = acc;
    }
    __syncthreads();
    if (tid < BB) scnt[tid] = soff[tid];   // reuse as cursors
    __syncthreads();
    for (int i = tid; i < n; i += blockDim.x) {
        int pos = atomicAdd(&scnt[ib[i]], 1);
        g_perm[pos] = i;
    }
}

// ---------------------------------------------------------------
// Kernel 4: attention. One block handles M_TILE queries of one batch image.
// 256 threads stride over p in [0,4096). Two passes: (1) row max,
// (2) exp/sum + weighted V accumulation. Block-wide butterfly+smem reduce.
// ---------------------------------------------------------------
__global__ void __launch_bounds__(256, 2)
attn_kernel(const float* __restrict__ x,
            const int* __restrict__ ih, const int* __restrict__ iw,
            const float* __restrict__ gamma, float* __restrict__ y) {
    int b = blockIdx.y;
    int tid = threadIdx.x;
    int start = g_off[b], end = g_off[b + 1];
    int base = start + blockIdx.x * M_TILE;
    if (base >= end) return;
    int mcnt = min(M_TILE, end - base);

    __shared__ int   s_n[M_TILE];
    __shared__ float s_max[M_TILE * 8];
    __shared__ float s_red[M_TILE * 6 * 8];

    if (tid < M_TILE) s_n[tid] = (tid < mcnt) ? g_perm[base + tid] : -1;
    __syncthreads();

    float q[M_TILE][CC];
#pragma unroll
    for (int m = 0; m < M_TILE; m++) {
        int n = s_n[m];
#pragma unroll
        for (int c = 0; c < CC; c++)
            q[m][c] = (n >= 0) ? __ldg(&g_q[n * CC + c]) : 0.0f;
    }

    const float* kf = g_kf + b * BSTRIDE;
    const float* vf = g_vf + b * BSTRIDE;

    // ---- pass 1: per-row max ----
    float rmax[M_TILE];
#pragma unroll
    for (int m = 0; m < M_TILE; m++) rmax[m] = -3.0e38f;

    for (int p = tid; p < HW; p += 256) {
        float k0 = kf[p];
        float k1 = kf[HW + p];
        float k2 = kf[2 * HW + p];
        float k3 = kf[3 * HW + p];
        float k4 = kf[4 * HW + p];
#pragma unroll
        for (int m = 0; m < M_TILE; m++) {
            float e = q[m][0] * k0;
            e = fmaf(q[m][1], k1, e);
            e = fmaf(q[m][2], k2, e);
            e = fmaf(q[m][3], k3, e);
            e = fmaf(q[m][4], k4, e);
            rmax[m] = fmaxf(rmax[m], e);
        }
    }
    // warp butterfly
#pragma unroll
    for (int m = 0; m < M_TILE; m++) {
#pragma unroll
        for (int off = 16; off > 0; off >>= 1)
            rmax[m] = fmaxf(rmax[m], __shfl_xor_sync(0xffffffffu, rmax[m], off));
    }
    int wid = tid >> 5, lane = tid & 31;
    if (lane == 0) {
#pragma unroll
        for (int m = 0; m < M_TILE; m++) s_max[m * 8 + wid] = rmax[m];
    }
    __syncthreads();
#pragma unroll
    for (int m = 0; m < M_TILE; m++) {
        float v = s_max[m * 8];
#pragma unroll
        for (int w = 1; w < 8; w++) v = fmaxf(v, s_max[m * 8 + w]);
        rmax[m] = v;
    }

    // ---- pass 2: exp/sum + weighted V ----
    float ssum[M_TILE];
    float oacc[M_TILE][CC];
#pragma unroll
    for (int m = 0; m < M_TILE; m++) {
        ssum[m] = 0.0f;
#pragma unroll
        for (int c = 0; c < CC; c++) oacc[m][c] = 0.0f;
    }

    for (int p = tid; p < HW; p += 256) {
        float k0 = kf[p];
        float k1 = kf[HW + p];
        float k2 = kf[2 * HW + p];
        float k3 = kf[3 * HW + p];
        float k4 = kf[4 * HW + p];
        float v0 = vf[p];
        float v1 = vf[HW + p];
        float v2 = vf[2 * HW + p];
        float v3 = vf[3 * HW + p];
        float v4 = vf[4 * HW + p];
#pragma unroll
        for (int m = 0; m < M_TILE; m++) {
            float e = q[m][0] * k0;
            e = fmaf(q[m][1], k1, e);
            e = fmaf(q[m][2], k2, e);
            e = fmaf(q[m][3], k3, e);
            e = fmaf(q[m][4], k4, e);
            float w = __expf(e - rmax[m]);
            ssum[m] += w;
            oacc[m][0] = fmaf(w, v0, oacc[m][0]);
            oacc[m][1] = fmaf(w, v1, oacc[m][1]);
            oacc[m][2] = fmaf(w, v2, oacc[m][2]);
            oacc[m][3] = fmaf(w, v3, oacc[m][3]);
            oacc[m][4] = fmaf(w, v4, oacc[m][4]);
        }
    }

    // warp butterfly for 48 values
#pragma unroll
    for (int m = 0; m < M_TILE; m++) {
#pragma unroll
        for (int off = 16; off > 0; off >>= 1)
            ssum[m] += __shfl_xor_sync(0xffffffffu, ssum[m], off);
#pragma unroll
        for (int c = 0; c < CC; c++) {
#pragma unroll
            for (int off = 16; off > 0; off >>= 1)
                oacc[m][c] += __shfl_xor_sync(0xffffffffu, oacc[m][c], off);
        }
    }
    if (lane == 0) {
#pragma unroll
        for (int m = 0; m < M_TILE; m++) {
            s_red[(m * 6 + 0) * 8 + wid] = ssum[m];
#pragma unroll
            for (int c = 0; c < CC; c++)
                s_red[(m * 6 + 1 + c) * 8 + wid] = oacc[m][c];
        }
    }
    __syncthreads();

    // ---- final: thread m writes its query's 5 channels ----
    if (tid < mcnt) {
        int m = tid;
        float s = 0.0f;
#pragma unroll
        for (int w = 0; w < 8; w++) s += s_red[(m * 6) * 8 + w];
        float inv = 1.0f / s;
        float g = gamma[0];
        int n = s_n[m];
        int pix = ih[n] * WW + iw[n];
#pragma unroll
        for (int c = 0; c < CC; c++) {
            float oc = 0.0f;
#pragma unroll
            for (int w = 0; w < 8; w++) oc += s_red[(m * 6 + 1 + c) * 8 + w];
            int idx = b * BSTRIDE + c * HW + pix;
            y[idx] = fmaf(g, oc * inv, x[idx]);
        }
    }
}

// ---------------------------------------------------------------
// launch
// ---------------------------------------------------------------
extern "C" void kernel_launch(void* const* d_in, const int* in_sizes, int n_in,
                              void* d_out, int out_size) {
    const float* x     = (const float*)d_in[0];
    // d_in[1] = x_teature (unused by reference)
    const float* qw    = (const float*)d_in[2];
    const float* qb    = (const float*)d_in[3];
    const float* kw    = (const float*)d_in[4];
    const float* kb    = (const float*)d_in[5];
    const float* vw    = (const float*)d_in[6];
    const float* vb    = (const float*)d_in[7];
    const float* gamma = (const float*)d_in[8];
    const int*   ib    = (const int*)d_in[9];
    const int*   ih    = (const int*)d_in[10];
    const int*   iw    = (const int*)d_in[11];
    float* y = (float*)d_out;

    int n = in_sizes[9];  // index_len (== idx_b element count)

    kv_kernel<<<(BB * HW) / 256, 256>>>(x, kw, kb, vw, vb, y);
    q_kernel<<<(n + 255) / 256, 256>>>(x, qw, qb, ib, ih, iw, n);
    group_kernel<<<1, 256>>>(ib, n);

    dim3 grid((n + M_TILE - 1) / M_TILE, BB);
    attn_kernel<<<grid, 256>>>(x, ih, iw, gamma, y);
}

// round 2
// speedup vs baseline: 1.1764x; 1.1764x over previous
#include <cuda_runtime.h>
#include <cuda_bf16.h>

// Problem constants: B=4, C=5, H=64, W=64, N=4096
#define BB 4
#define CC 5
#define WW 64
#define HW 4096
#define BSTRIDE 20480      // C*HW
#define NMAX 4096
#define M_TILE 8
#define LOG2E 1.4426950408889634f

// -------- scratch (device globals; no allocation allowed) --------
__device__ float g_kf[BB * CC * HW];
__device__ float g_vf[BB * CC * HW];
__device__ float g_q[NMAX * CC];        // log2(e)-scaled query projections
__device__ int   g_perm[NMAX];
__device__ int   g_off[BB + 1];
__device__ float g_pmin[64][CC];        // per-block partial k channel min
__device__ float g_pmax[64][CC];        // per-block partial k channel max
__device__ float g_pnrm[64];            // per-block partial max ||k||^2
__device__ float g_kmin[BB][CC];
__device__ float g_kmax[BB][CC];
__device__ float g_knrm[BB];            // max_p ||k_p|| per batch

__device__ __forceinline__ float ex2f(float x) {
    float r; asm("ex2.approx.f32 %0, %1;" : "=f"(r) : "f"(x)); return r;
}

// ---------------------------------------------------------------
// Kernel 1 (fused): blocks [0,64): k/v projection + y=x copy + per-block
// k statistics. blocks [64,...): q projection (log2-scaled).
// ---------------------------------------------------------------
__global__ void prep_kernel(const float* __restrict__ x,
                            const float* __restrict__ qw, const float* __restrict__ qb,
                            const float* __restrict__ kw, const float* __restrict__ kb,
                            const float* __restrict__ vw, const float* __restrict__ vb,
                            const int* __restrict__ ib, const int* __restrict__ ih,
                            const int* __restrict__ iw, int n,
                            float* __restrict__ y) {
    int tid = threadIdx.x;
    if (blockIdx.x < 64) {
        __shared__ float skw[25], skb[5], svw[25], svb[5];
        __shared__ float smin[8][CC], smax[8][CC], snrm[8];
        if (tid < 25) { skw[tid] = kw[tid]; svw[tid] = vw[tid]; }
        if (tid < 5)  { skb[tid] = kb[tid]; svb[tid] = vb[tid]; }
        __syncthreads();

        int t = blockIdx.x * 256 + tid;
        int b = t >> 12;
        int p = t & (HW - 1);
        const float* xb = x + b * BSTRIDE + p;
        float* yb = y + b * BSTRIDE + p;

        float xs[CC];
#pragma unroll
        for (int c = 0; c < CC; c++) { xs[c] = xb[c * HW]; yb[c * HW] = xs[c]; }

        float kk[CC]; float nrm = 0.0f;
#pragma unroll
        for (int o = 0; o < CC; o++) {
            float k = skb[o], v = svb[o];
#pragma unroll
            for (int c = 0; c < CC; c++) {
                k = fmaf(skw[o * CC + c], xs[c], k);
                v = fmaf(svw[o * CC + c], xs[c], v);
            }
            g_kf[b * BSTRIDE + o * HW + p] = k;
            g_vf[b * BSTRIDE + o * HW + p] = v;
            kk[o] = k;
            nrm = fmaf(k, k, nrm);
        }

        float mn[CC], mx[CC];
#pragma unroll
        for (int c = 0; c < CC; c++) { mn[c] = kk[c]; mx[c] = kk[c]; }
#pragma unroll
        for (int off = 16; off > 0; off >>= 1) {
#pragma unroll
            for (int c = 0; c < CC; c++) {
                mn[c] = fminf(mn[c], __shfl_xor_sync(0xffffffffu, mn[c], off));
                mx[c] = fmaxf(mx[c], __shfl_xor_sync(0xffffffffu, mx[c], off));
            }
            nrm = fmaxf(nrm, __shfl_xor_sync(0xffffffffu, nrm, off));
        }
        int wid = tid >> 5, lane = tid & 31;
        if (lane == 0) {
#pragma unroll
            for (int c = 0; c < CC; c++) { smin[wid][c] = mn[c]; smax[wid][c] = mx[c]; }
            snrm[wid] = nrm;
        }
        __syncthreads();
        if (tid < CC) {
            float a = smin[0][tid], bx = smax[0][tid];
#pragma unroll
            for (int w = 1; w < 8; w++) { a = fminf(a, smin[w][tid]); bx = fmaxf(bx, smax[w][tid]); }
            g_pmin[blockIdx.x][tid] = a;
            g_pmax[blockIdx.x][tid] = bx;
        }
        if (tid == CC) {
            float a = snrm[0];
#pragma unroll
            for (int w = 1; w < 8; w++) a = fmaxf(a, snrm[w]);
            g_pnrm[blockIdx.x] = a;
        }
    } else {
        __shared__ float sw[25], sb[5];
        if (tid < 25) sw[tid] = qw[tid];
        if (tid < 5)  sb[tid] = qb[tid];
        __syncthreads();
        int i = (blockIdx.x - 64) * 256 + tid;
        if (i >= n) return;
        int b = ib[i];
        int pix = ih[i] * WW + iw[i];
        const float* xb = x + b * BSTRIDE + pix;
        float xs[CC];
#pragma unroll
        for (int c = 0; c < CC; c++) xs[c] = xb[c * HW];
#pragma unroll
        for (int o = 0; o < CC; o++) {
            float q = sb[o];
#pragma unroll
            for (int c = 0; c < CC; c++) q = fmaf(sw[o * CC + c], xs[c], q);
            g_q[i * CC + o] = q * LOG2E;
        }
    }
}

// ---------------------------------------------------------------
// Kernel 2: group query indices by batch + reduce k-stat partials
// ---------------------------------------------------------------
__global__ void group_kernel(const int* __restrict__ ib, int n) {
    __shared__ int scnt[BB];
    __shared__ int soff[BB];
    int tid = threadIdx.x;

    // reduce k-stat partials (independent of grouping)
    if (tid < 40) {
        int b = tid / 10, r = tid % 10, c = r % 5;
        bool ismax = r >= 5;
        float acc = ismax ? -3.0e38f : 3.0e38f;
        for (int k = 0; k < 16; k++) {
            float v = ismax ? g_pmax[b * 16 + k][c] : g_pmin[b * 16 + k][c];
            acc = ismax ? fmaxf(acc, v) : fminf(acc, v);
        }
        if (ismax) g_kmax[b][c] = acc; else g_kmin[b][c] = acc;
    } else if (tid < 44) {
        int b = tid - 40;
        float a = 0.0f;
        for (int k = 0; k < 16; k++) a = fmaxf(a, g_pnrm[b * 16 + k]);
        g_knrm[b] = sqrtf(a);
    }

    if (tid < BB) scnt[tid] = 0;
    __syncthreads();
    for (int i = tid; i < n; i += blockDim.x) atomicAdd(&scnt[ib[i]], 1);
    __syncthreads();
    if (tid == 0) {
        int acc = 0;
        for (int b = 0; b < BB; b++) { g_off[b] = acc; soff[b] = acc; acc += scnt[b]; }
        g_off[BB] = acc;
    }
    __syncthreads();
    if (tid < BB) scnt[tid] = soff[tid];
    __syncthreads();
    for (int i = tid; i < n; i += blockDim.x) {
        int pos = atomicAdd(&scnt[ib[i]], 1);
        g_perm[pos] = i;
    }
}

// ---------------------------------------------------------------
// Kernel 3: one-pass bounded-softmax attention.
// One block = M_TILE queries of one batch; 256 threads stride over p.
// lmax starts at min(separable, Cauchy) upper bound - 32 (log2 units);
// online rescale guard keeps it exact if any energy exceeds it.
// ---------------------------------------------------------------
__global__ void __launch_bounds__(256, 2)
attn_kernel(const float* __restrict__ x,
            const int* __restrict__ ih, const int* __restrict__ iw,
            const float* __restrict__ gamma, float* __restrict__ y) {
    int b = blockIdx.y;
    int tid = threadIdx.x;
    int start = g_off[b], end = g_off[b + 1];
    int base = start + blockIdx.x * M_TILE;
    if (base >= end) return;
    int mcnt = min(M_TILE, end - base);

    __shared__ int   s_n[M_TILE];
    __shared__ float s_max[M_TILE * 8];
    __shared__ float s_red[M_TILE * 6 * 8];

    if (tid < M_TILE) s_n[tid] = (tid < mcnt) ? g_perm[base + tid] : -1;
    __syncthreads();

    float q[M_TILE][CC];
#pragma unroll
    for (int m = 0; m < M_TILE; m++) {
        int n = s_n[m];
#pragma unroll
        for (int c = 0; c < CC; c++)
            q[m][c] = (n >= 0) ? __ldg(&g_q[n * CC + c]) : 0.0f;
    }

    // per-m initial running max = min(separable, Cauchy) bound - 32 (log2)
    float kmx[CC], kmn[CC];
#pragma unroll
    for (int c = 0; c < CC; c++) { kmx[c] = g_kmax[b][c]; kmn[c] = g_kmin[b][c]; }
    float knrm = g_knrm[b];

    float lmax[M_TILE];
#pragma unroll
    for (int m = 0; m < M_TILE; m++) {
        float sep = 0.0f, qq = 0.0f;
#pragma unroll
        for (int c = 0; c < CC; c++) {
            sep += fmaxf(q[m][c] * kmx[c], q[m][c] * kmn[c]);
            qq = fmaf(q[m][c], q[m][c], qq);
        }
        float cau = sqrtf(qq) * knrm;
        lmax[m] = fminf(sep, cau) - 32.0f;
    }

    const float* kf = g_kf + b * BSTRIDE;
    const float* vf = g_vf + b * BSTRIDE;

    float ssum[M_TILE];
    float oacc[M_TILE][CC];
#pragma unroll
    for (int m = 0; m < M_TILE; m++) {
        ssum[m] = 0.0f;
#pragma unroll
        for (int c = 0; c < CC; c++) oacc[m][c] = 0.0f;
    }

    for (int p = tid; p < HW; p += 256) {
        float k0 = kf[p];
        float k1 = kf[HW + p];
        float k2 = kf[2 * HW + p];
        float k3 = kf[3 * HW + p];
        float k4 = kf[4 * HW + p];
        float v0 = vf[p];
        float v1 = vf[HW + p];
        float v2 = vf[2 * HW + p];
        float v3 = vf[3 * HW + p];
        float v4 = vf[4 * HW + p];
#pragma unroll
        for (int m = 0; m < M_TILE; m++) {
            float e = q[m][0] * k0;
            e = fmaf(q[m][1], k1, e);
            e = fmaf(q[m][2], k2, e);
            e = fmaf(q[m][3], k3, e);
            e = fmaf(q[m][4], k4, e);
            if (e > lmax[m]) {              // rare: bound was within 32 log2 units
                float r = ex2f(lmax[m] - e);
                ssum[m] *= r;
                oacc[m][0] *= r; oacc[m][1] *= r; oacc[m][2] *= r;
                oacc[m][3] *= r; oacc[m][4] *= r;
                lmax[m] = e;
            }
            float w = ex2f(e - lmax[m]);
            ssum[m] += w;
            oacc[m][0] = fmaf(w, v0, oacc[m][0]);
            oacc[m][1] = fmaf(w, v1, oacc[m][1]);
            oacc[m][2] = fmaf(w, v2, oacc[m][2]);
            oacc[m][3] = fmaf(w, v3, oacc[m][3]);
            oacc[m][4] = fmaf(w, v4, oacc[m][4]);
        }
    }

    int wid = tid >> 5, lane = tid & 31;

    // ---- align running maxes: warp stage ----
#pragma unroll
    for (int m = 0; m < M_TILE; m++) {
        float own = lmax[m];
        float wm = own;
#pragma unroll
        for (int off = 16; off > 0; off >>= 1)
            wm = fmaxf(wm, __shfl_xor_sync(0xffffffffu, wm, off));
        float r = ex2f(own - wm);
        ssum[m] *= r;
#pragma unroll
        for (int c = 0; c < CC; c++) oacc[m][c] *= r;
        lmax[m] = wm;
    }
    if (lane == 0) {
#pragma unroll
        for (int m = 0; m < M_TILE; m++) s_max[m * 8 + wid] = lmax[m];
    }
    __syncthreads();
#pragma unroll
    for (int m = 0; m < M_TILE; m++) {
        float g = s_max[m * 8];
#pragma unroll
        for (int w = 1; w < 8; w++) g = fmaxf(g, s_max[m * 8 + w]);
        float r = ex2f(lmax[m] - g);
        ssum[m] *= r;
#pragma unroll
        for (int c = 0; c < CC; c++) oacc[m][c] *= r;
    }

    // ---- sum reduction ----
#pragma unroll
    for (int m = 0; m < M_TILE; m++) {
#pragma unroll
        for (int off = 16; off > 0; off >>= 1)
            ssum[m] += __shfl_xor_sync(0xffffffffu, ssum[m], off);
#pragma unroll
        for (int c = 0; c < CC; c++) {
#pragma unroll
            for (int off = 16; off > 0; off >>= 1)
                oacc[m][c] += __shfl_xor_sync(0xffffffffu, oacc[m][c], off);
        }
    }
    if (lane == 0) {
#pragma unroll
        for (int m = 0; m < M_TILE; m++) {
            s_red[(m * 6 + 0) * 8 + wid] = ssum[m];
#pragma unroll
            for (int c = 0; c < CC; c++)
                s_red[(m * 6 + 1 + c) * 8 + wid] = oacc[m][c];
        }
    }
    __syncthreads();

    if (tid < mcnt) {
        int m = tid;
        float s = 0.0f;
#pragma unroll
        for (int w = 0; w < 8; w++) s += s_red[(m * 6) * 8 + w];
        float inv = 1.0f / s;
        float g = gamma[0];
        int n = s_n[m];
        int pix = ih[n] * WW + iw[n];
#pragma unroll
        for (int c = 0; c < CC; c++) {
            float oc = 0.0f;
#pragma unroll
            for (int w = 0; w < 8; w++) oc += s_red[(m * 6 + 1 + c) * 8 + w];
            int idx = b * BSTRIDE + c * HW + pix;
            y[idx] = fmaf(g, oc * inv, x[idx]);
        }
    }
}

// ---------------------------------------------------------------
// launch
// ---------------------------------------------------------------
extern "C" void kernel_launch(void* const* d_in, const int* in_sizes, int n_in,
                              void* d_out, int out_size) {
    const float* x     = (const float*)d_in[0];
    const float* qw    = (const float*)d_in[2];
    const float* qb    = (const float*)d_in[3];
    const float* kw    = (const float*)d_in[4];
    const float* kb    = (const float*)d_in[5];
    const float* vw    = (const float*)d_in[6];
    const float* vb    = (const float*)d_in[7];
    const float* gamma = (const float*)d_in[8];
    const int*   ib    = (const int*)d_in[9];
    const int*   ih    = (const int*)d_in[10];
    const int*   iw    = (const int*)d_in[11];
    float* y = (float*)d_out;

    int n = in_sizes[9];

    int qblocks = (n + 255) / 256;
    prep_kernel<<<64 + qblocks, 256>>>(x, qw, qb, kw, kb, vw, vb, ib, ih, iw, n, y);
    group_kernel<<<1, 256>>>(ib, n);

    dim3 grid((n + M_TILE - 1) / M_TILE, BB);
    attn_kernel<<<grid, 256>>>(x, ih, iw, gamma, y);
}

// round 3
// speedup vs baseline: 1.5733x; 1.3374x over previous
#include <cuda_runtime.h>
#include <cuda_bf16.h>

// Problem constants: B=4, C=5, H=64, W=64, N=4096
#define BB 4
#define CC 5
#define WW 64
#define HW 4096
#define BSTRIDE 20480      // C*HW
#define NMAX 4096
#define M_TILE 8
#define LOG2E 1.4426950408889634f

// -------- scratch (device globals; no allocation allowed) --------
__device__ float g_kf[BB * CC * HW];
__device__ float g_vf[BB * CC * HW];
__device__ float g_q[NMAX * CC];        // log2(e)-scaled query projections
__device__ int   g_perm[NMAX];
__device__ int   g_off[BB + 1];
__device__ float g_pmin[64][CC];        // per-block partial k channel min
__device__ float g_pmax[64][CC];        // per-block partial k channel max
__device__ float g_pnrm[64];            // per-block partial max ||k||^2

__device__ __forceinline__ float ex2f(float x) {
    float r; asm("ex2.approx.f32 %0, %1;" : "=f"(r) : "f"(x)); return r;
}

// ---------------------------------------------------------------
// Kernel 1 (fused):
//   blocks [0,64)            : k/v projection + y=x copy + per-block k stats
//   blocks [64, 64+qblocks)  : q projection (log2-scaled)
//   last block               : counting sort of query indices by batch
// ---------------------------------------------------------------
__global__ void prep_kernel(const float* __restrict__ x,
                            const float* __restrict__ qw, const float* __restrict__ qb,
                            const float* __restrict__ kw, const float* __restrict__ kb,
                            const float* __restrict__ vw, const float* __restrict__ vb,
                            const int* __restrict__ ib, const int* __restrict__ ih,
                            const int* __restrict__ iw, int n,
                            float* __restrict__ y) {
    int tid = threadIdx.x;
    if (blockIdx.x < 64) {
        __shared__ float skw[25], skb[5], svw[25], svb[5];
        __shared__ float smin[8][CC], smax[8][CC], snrm[8];
        if (tid < 25) { skw[tid] = kw[tid]; svw[tid] = vw[tid]; }
        if (tid < 5)  { skb[tid] = kb[tid]; svb[tid] = vb[tid]; }
        __syncthreads();

        int t = blockIdx.x * 256 + tid;
        int b = t >> 12;
        int p = t & (HW - 1);
        const float* xb = x + b * BSTRIDE + p;
        float* yb = y + b * BSTRIDE + p;

        float xs[CC];
#pragma unroll
        for (int c = 0; c < CC; c++) { xs[c] = xb[c * HW]; yb[c * HW] = xs[c]; }

        float kk[CC]; float nrm = 0.0f;
#pragma unroll
        for (int o = 0; o < CC; o++) {
            float k = skb[o], v = svb[o];
#pragma unroll
            for (int c = 0; c < CC; c++) {
                k = fmaf(skw[o * CC + c], xs[c], k);
                v = fmaf(svw[o * CC + c], xs[c], v);
            }
            g_kf[b * BSTRIDE + o * HW + p] = k;
            g_vf[b * BSTRIDE + o * HW + p] = v;
            kk[o] = k;
            nrm = fmaf(k, k, nrm);
        }

        float mn[CC], mx[CC];
#pragma unroll
        for (int c = 0; c < CC; c++) { mn[c] = kk[c]; mx[c] = kk[c]; }
#pragma unroll
        for (int off = 16; off > 0; off >>= 1) {
#pragma unroll
            for (int c = 0; c < CC; c++) {
                mn[c] = fminf(mn[c], __shfl_xor_sync(0xffffffffu, mn[c], off));
                mx[c] = fmaxf(mx[c], __shfl_xor_sync(0xffffffffu, mx[c], off));
            }
            nrm = fmaxf(nrm, __shfl_xor_sync(0xffffffffu, nrm, off));
        }
        int wid = tid >> 5, lane = tid & 31;
        if (lane == 0) {
#pragma unroll
            for (int c = 0; c < CC; c++) { smin[wid][c] = mn[c]; smax[wid][c] = mx[c]; }
            snrm[wid] = nrm;
        }
        __syncthreads();
        if (tid < CC) {
            float a = smin[0][tid], bx = smax[0][tid];
#pragma unroll
            for (int w = 1; w < 8; w++) { a = fminf(a, smin[w][tid]); bx = fmaxf(bx, smax[w][tid]); }
            g_pmin[blockIdx.x][tid] = a;
            g_pmax[blockIdx.x][tid] = bx;
        }
        if (tid == CC) {
            float a = snrm[0];
#pragma unroll
            for (int w = 1; w < 8; w++) a = fmaxf(a, snrm[w]);
            g_pnrm[blockIdx.x] = a;
        }
    } else if (blockIdx.x < gridDim.x - 1) {
        __shared__ float sw[25], sb[5];
        if (tid < 25) sw[tid] = qw[tid];
        if (tid < 5)  sb[tid] = qb[tid];
        __syncthreads();
        int i = (blockIdx.x - 64) * 256 + tid;
        if (i >= n) return;
        int b = ib[i];
        int pix = ih[i] * WW + iw[i];
        const float* xb = x + b * BSTRIDE + pix;
        float xs[CC];
#pragma unroll
        for (int c = 0; c < CC; c++) xs[c] = xb[c * HW];
#pragma unroll
        for (int o = 0; o < CC; o++) {
            float q = sb[o];
#pragma unroll
            for (int c = 0; c < CC; c++) q = fmaf(sw[o * CC + c], xs[c], q);
            g_q[i * CC + o] = q * LOG2E;
        }
    } else {
        // counting sort of query indices by batch (single block)
        __shared__ int scnt[BB];
        __shared__ int soff[BB];
        if (tid < BB) scnt[tid] = 0;
        __syncthreads();
        for (int i = tid; i < n; i += blockDim.x) atomicAdd(&scnt[ib[i]], 1);
        __syncthreads();
        if (tid == 0) {
            int acc = 0;
            for (int b = 0; b < BB; b++) { g_off[b] = acc; soff[b] = acc; acc += scnt[b]; }
            g_off[BB] = acc;
        }
        __syncthreads();
        if (tid < BB) scnt[tid] = soff[tid];
        __syncthreads();
        for (int i = tid; i < n; i += blockDim.x) {
            int pos = atomicAdd(&scnt[ib[i]], 1);
            g_perm[pos] = i;
        }
    }
}

// ---------------------------------------------------------------
// Kernel 2: one-pass bounded-softmax attention, guard-free.
// lmax = min(separable, Cauchy) upper bound - 32 (log2 units) is a TRUE
// upper bound on every energy, uniform across the block -> weights <= 2^32,
// row sums <= 2^44, no overflow, no guard, no max alignment needed.
// One block = M_TILE queries of one batch; 256 threads, float2 over p.
// ---------------------------------------------------------------
__global__ void __launch_bounds__(256, 2)
attn_kernel(const float* __restrict__ x,
            const int* __restrict__ ih, const int* __restrict__ iw,
            const float* __restrict__ gamma, float* __restrict__ y) {
    int b = blockIdx.y;
    int tid = threadIdx.x;
    int start = g_off[b], end = g_off[b + 1];
    int base = start + blockIdx.x * M_TILE;
    if (base >= end) return;
    int mcnt = min(M_TILE, end - base);

    __shared__ int   s_n[M_TILE];
    __shared__ float s_kmn[CC], s_kmx[CC], s_knrm;
    __shared__ float s_red[M_TILE * 6 * 8];

    if (tid < M_TILE) s_n[tid] = (tid < mcnt) ? g_perm[base + tid] : -1;
    // finalize per-batch k stats from the 16 partials (cheap, per block)
    if (tid >= 32 && tid < 32 + CC) {
        int c = tid - 32;
        float a = 3.0e38f;
#pragma unroll
        for (int k = 0; k < 16; k++) a = fminf(a, g_pmin[b * 16 + k][c]);
        s_kmn[c] = a;
    } else if (tid >= 64 && tid < 64 + CC) {
        int c = tid - 64;
        float a = -3.0e38f;
#pragma unroll
        for (int k = 0; k < 16; k++) a = fmaxf(a, g_pmax[b * 16 + k][c]);
        s_kmx[c] = a;
    } else if (tid == 96) {
        float a = 0.0f;
#pragma unroll
        for (int k = 0; k < 16; k++) a = fmaxf(a, g_pnrm[b * 16 + k]);
        s_knrm = sqrtf(a);
    }
    __syncthreads();

    float q[M_TILE][CC];
#pragma unroll
    for (int m = 0; m < M_TILE; m++) {
        int n = s_n[m];
#pragma unroll
        for (int c = 0; c < CC; c++)
            q[m][c] = (n >= 0) ? __ldg(&g_q[n * CC + c]) : 0.0f;
    }

    // nlmax[m] = 32 - min(separable, Cauchy) upper bound (block-uniform)
    float nlmax[M_TILE];
    {
        float knrm = s_knrm;
#pragma unroll
        for (int m = 0; m < M_TILE; m++) {
            float sep = 0.0f, qq = 0.0f;
#pragma unroll
            for (int c = 0; c < CC; c++) {
                sep += fmaxf(q[m][c] * s_kmx[c], q[m][c] * s_kmn[c]);
                qq = fmaf(q[m][c], q[m][c], qq);
            }
            float cau = sqrtf(qq) * knrm;
            nlmax[m] = 32.0f - fminf(sep, cau);
        }
    }

    const float2* kf2 = (const float2*)(g_kf + b * BSTRIDE);
    const float2* vf2 = (const float2*)(g_vf + b * BSTRIDE);

    float ssum[M_TILE];
    float oacc[M_TILE][CC];
#pragma unroll
    for (int m = 0; m < M_TILE; m++) {
        ssum[m] = 0.0f;
#pragma unroll
        for (int c = 0; c < CC; c++) oacc[m][c] = 0.0f;
    }

#pragma unroll 1
    for (int it = 0; it < 8; it++) {
        int p2 = tid + it * 256;           // float2 index, 2048 per channel
        float2 k0 = kf2[p2];
        float2 k1 = kf2[2048 + p2];
        float2 k2 = kf2[2 * 2048 + p2];
        float2 k3 = kf2[3 * 2048 + p2];
        float2 k4 = kf2[4 * 2048 + p2];
        float2 v0 = vf2[p2];
        float2 v1 = vf2[2048 + p2];
        float2 v2 = vf2[2 * 2048 + p2];
        float2 v3 = vf2[3 * 2048 + p2];
        float2 v4 = vf2[4 * 2048 + p2];
#pragma unroll
        for (int m = 0; m < M_TILE; m++) {
            float ex = fmaf(q[m][0], k0.x, nlmax[m]);
            ex = fmaf(q[m][1], k1.x, ex);
            ex = fmaf(q[m][2], k2.x, ex);
            ex = fmaf(q[m][3], k3.x, ex);
            ex = fmaf(q[m][4], k4.x, ex);
            float ey = fmaf(q[m][0], k0.y, nlmax[m]);
            ey = fmaf(q[m][1], k1.y, ey);
            ey = fmaf(q[m][2], k2.y, ey);
            ey = fmaf(q[m][3], k3.y, ey);
            ey = fmaf(q[m][4], k4.y, ey);
            float wx = ex2f(ex);
            float wy = ex2f(ey);
            ssum[m] += wx + wy;
            oacc[m][0] = fmaf(wx, v0.x, fmaf(wy, v0.y, oacc[m][0]));
            oacc[m][1] = fmaf(wx, v1.x, fmaf(wy, v1.y, oacc[m][1]));
            oacc[m][2] = fmaf(wx, v2.x, fmaf(wy, v2.y, oacc[m][2]));
            oacc[m][3] = fmaf(wx, v3.x, fmaf(wy, v3.y, oacc[m][3]));
            oacc[m][4] = fmaf(wx, v4.x, fmaf(wy, v4.y, oacc[m][4]));
        }
    }

    int wid = tid >> 5, lane = tid & 31;

    // ---- sum reduction (lmax uniform -> plain sums) ----
#pragma unroll
    for (int m = 0; m < M_TILE; m++) {
#pragma unroll
        for (int off = 16; off > 0; off >>= 1)
            ssum[m] += __shfl_xor_sync(0xffffffffu, ssum[m], off);
#pragma unroll
        for (int c = 0; c < CC; c++) {
#pragma unroll
            for (int off = 16; off > 0; off >>= 1)
                oacc[m][c] += __shfl_xor_sync(0xffffffffu, oacc[m][c], off);
        }
    }
    if (lane == 0) {
#pragma unroll
        for (int m = 0; m < M_TILE; m++) {
            s_red[(m * 6 + 0) * 8 + wid] = ssum[m];
#pragma unroll
            for (int c = 0; c < CC; c++)
                s_red[(m * 6 + 1 + c) * 8 + wid] = oacc[m][c];
        }
    }
    __syncthreads();

    if (tid < mcnt) {
        int m = tid;
        float s = 0.0f;
#pragma unroll
        for (int w = 0; w < 8; w++) s += s_red[(m * 6) * 8 + w];
        float inv = 1.0f / s;
        float g = gamma[0];
        int n = s_n[m];
        int pix = ih[n] * WW + iw[n];
#pragma unroll
        for (int c = 0; c < CC; c++) {
            float oc = 0.0f;
#pragma unroll
            for (int w = 0; w < 8; w++) oc += s_red[(m * 6 + 1 + c) * 8 + w];
            int idx = b * BSTRIDE + c * HW + pix;
            y[idx] = fmaf(g, oc * inv, x[idx]);
        }
    }
}

// ---------------------------------------------------------------
// launch
// ---------------------------------------------------------------
extern "C" void kernel_launch(void* const* d_in, const int* in_sizes, int n_in,
                              void* d_out, int out_size) {
    const float* x     = (const float*)d_in[0];
    const float* qw    = (const float*)d_in[2];
    const float* qb    = (const float*)d_in[3];
    const float* kw    = (const float*)d_in[4];
    const float* kb    = (const float*)d_in[5];
    const float* vw    = (const float*)d_in[6];
    const float* vb    = (const float*)d_in[7];
    const float* gamma = (const float*)d_in[8];
    const int*   ib    = (const int*)d_in[9];
    const int*   ih    = (const int*)d_in[10];
    const int*   iw    = (const int*)d_in[11];
    float* y = (float*)d_out;

    int n = in_sizes[9];
    int qblocks = (n + 255) / 256;

    prep_kernel<<<64 + qblocks + 1, 256>>>(x, qw, qb, kw, kb, vw, vb, ib, ih, iw, n, y);

    dim3 grid((n + M_TILE - 1) / M_TILE, BB);
    attn_kernel<<<grid, 256>>>(x, ih, iw, gamma, y);
}